// round 4
// baseline (speedup 1.0000x reference)
#include <cuda_runtime.h>
#include <cfloat>
#include <cstdio>

// ---------------------------------------------------------------------------
// Problem constants
// ---------------------------------------------------------------------------
static constexpr int NBATCH   = 8192;
static constexpr int DBODY    = 64;
static constexpr int DOBJ     = 128;
static constexpr int NOBJ     = 9;
static constexpr int NEDGE    = 72;
static constexpr int DEDGE    = 128;
static constexpr int NISO     = 3;
static constexpr int NNODE    = NOBJ + NISO;      // 12
static constexpr int HID      = 256;
static constexpr int PHI_OUT  = 256;
static constexpr int ACT      = 32;
static constexpr int OBS_LD   = DBODY + NOBJ * DOBJ;  // 1216

// ---------------------------------------------------------------------------
// Scratch (device globals -- no dynamic allocation allowed)
// ---------------------------------------------------------------------------
__device__ float g_Xnf[(size_t)NNODE * NBATCH * 256];     // packed [node|feat] per (n,b)
__device__ float g_Cbody[(size_t)NBATCH * HID];           // body @ W1[:64]
__device__ float g_H[(size_t)NNODE * NBATCH * HID];       // layer-1 activations
__device__ float g_P[(size_t)NNODE * NBATCH * PHI_OUT];   // layer-2 activations
__device__ float g_pooled[(size_t)NBATCH * PHI_OUT];
__device__ float g_R[(size_t)NBATCH * HID];
__device__ int   g_seglist[NOBJ * NEDGE];
__device__ int   g_segcnt[NOBJ];

// ---------------------------------------------------------------------------
// K0: build segment lists from edges_to (generic, honors the input array)
// ---------------------------------------------------------------------------
__global__ void seg_kernel(const int* __restrict__ edges_to) {
    if (threadIdx.x == 0 && blockIdx.x == 0) {
        for (int n = 0; n < NOBJ; ++n) {
            int c = 0;
            for (int e = 0; e < NEDGE; ++e)
                if (edges_to[e] == n) g_seglist[n * NEDGE + c++] = e;
            g_segcnt[n] = c;
        }
    }
}

// ---------------------------------------------------------------------------
// K1: segment-max over incoming edges + pack Xnf[n*B+b] = [node(128) | feat(128)]
// grid: NNODE*NBATCH blocks of 128 threads
// ---------------------------------------------------------------------------
__global__ void pack_kernel(const float* __restrict__ obs,
                            const float* __restrict__ edges,
                            const float* __restrict__ iso,
                            const float* __restrict__ isof) {
    int n     = blockIdx.x % NNODE;
    size_t b  = blockIdx.x / NNODE;
    int d     = threadIdx.x;                       // 0..127

    float node, feat;
    if (n < NOBJ) {
        node = obs[b * OBS_LD + DBODY + (size_t)n * DOBJ + d];
        float m = -FLT_MAX;
        int cnt = g_segcnt[n];
        for (int k = 0; k < cnt; ++k) {
            int e = g_seglist[n * NEDGE + k];
            m = fmaxf(m, edges[(b * NEDGE + e) * DEDGE + d]);
        }
        feat = m;
    } else {
        int i = n - NOBJ;
        node = iso [(b * NISO + i) * DOBJ + d];
        feat = isof[(b * NISO + i) * DEDGE + d];
    }
    size_t row = (size_t)n * NBATCH + b;
    g_Xnf[row * 256 + d]       = node;
    g_Xnf[row * 256 + 128 + d] = feat;
}

// ---------------------------------------------------------------------------
// Generic 128x128-tile SGEMM: C[M,N] = op(A[M,K] @ B[K,N] (+bias) (+rowadd) (relu))
// 256 threads, 8x8 per thread, single-buffer smem with register prefetch.
// rowadd (if enabled) is indexed rowadd[(row & rowmask) * 256 + col].
// ---------------------------------------------------------------------------
template<bool RELU, bool ROWADD>
__global__ __launch_bounds__(256, 2)
void gemm128_kernel(const float* __restrict__ A, int lda,
                    const float* __restrict__ Bw, int ldb,
                    float* __restrict__ C, int ldc,
                    int K,
                    const float* __restrict__ bias,
                    const float* __restrict__ rowadd,
                    int rowmask) {
    const int tid = threadIdx.x;
    const int m0  = blockIdx.y * 128;
    const int n0  = blockIdx.x * 128;

    __shared__ float sA[8][132];   // [k][m], padded
    __shared__ float sB[8][132];   // [k][n], padded (132*4B = 528B rows, 16B aligned)

    float acc[8][8];
#pragma unroll
    for (int i = 0; i < 8; ++i)
#pragma unroll
        for (int j = 0; j < 8; ++j) acc[i][j] = 0.f;

    // global load mapping
    const int arow  = tid >> 1;            // 0..127
    const int akoff = (tid & 1) * 4;       // 0 or 4
    const int bkrow = tid >> 5;            // 0..7
    const int bcol  = (tid & 31) * 4;      // 0..124

    const float* Aptr = A + (size_t)(m0 + arow) * lda + akoff;
    const float* Bptr = Bw + (size_t)bkrow * ldb + n0 + bcol;

    const int kIter = K >> 3;
    float4 pa = *(const float4*)Aptr;
    float4 pb = *(const float4*)Bptr;

    const int ty = tid >> 4, tx = tid & 15;
    const int r0 = ty * 4, r1 = 64 + ty * 4;
    const int c0 = tx * 4, c1 = 64 + tx * 4;

    for (int t = 0; t < kIter; ++t) {
        sA[akoff + 0][arow] = pa.x;
        sA[akoff + 1][arow] = pa.y;
        sA[akoff + 2][arow] = pa.z;
        sA[akoff + 3][arow] = pa.w;
        *(float4*)&sB[bkrow][bcol] = pb;
        __syncthreads();
        if (t + 1 < kIter) {
            pa = *(const float4*)(Aptr + (size_t)(t + 1) * 8);
            pb = *(const float4*)(Bptr + (size_t)(t + 1) * 8 * ldb);
        }
#pragma unroll
        for (int kk = 0; kk < 8; ++kk) {
            float a[8], b[8];
            *(float4*)&a[0] = *(const float4*)&sA[kk][r0];
            *(float4*)&a[4] = *(const float4*)&sA[kk][r1];
            *(float4*)&b[0] = *(const float4*)&sB[kk][c0];
            *(float4*)&b[4] = *(const float4*)&sB[kk][c1];
#pragma unroll
            for (int i = 0; i < 8; ++i)
#pragma unroll
                for (int j = 0; j < 8; ++j)
                    acc[i][j] = fmaf(a[i], b[j], acc[i][j]);
        }
        __syncthreads();
    }

    // epilogue
    float4 bv0 = make_float4(0.f, 0.f, 0.f, 0.f), bv1 = bv0;
    if (bias) {
        bv0 = *(const float4*)&bias[n0 + c0];
        bv1 = *(const float4*)&bias[n0 + c1];
    }
#pragma unroll
    for (int i = 0; i < 8; ++i) {
        int rr = (i < 4) ? (r0 + i) : (r1 + i - 4);
        size_t row = (size_t)m0 + rr;
        float4 ad0 = make_float4(0.f, 0.f, 0.f, 0.f), ad1 = ad0;
        if (ROWADD) {
            const float* rp = rowadd + ((size_t)((int)row & rowmask) << 8);
            ad0 = *(const float4*)&rp[n0 + c0];
            ad1 = *(const float4*)&rp[n0 + c1];
        }
        float o[8];
#pragma unroll
        for (int j = 0; j < 4; ++j) o[j]     = acc[i][j]     + (&bv0.x)[j] + (&ad0.x)[j];
#pragma unroll
        for (int j = 0; j < 4; ++j) o[4 + j] = acc[i][4 + j] + (&bv1.x)[j] + (&ad1.x)[j];
        if (RELU) {
#pragma unroll
            for (int j = 0; j < 8; ++j) o[j] = fmaxf(o[j], 0.f);
        }
        *(float4*)&C[row * ldc + n0 + c0] = *(float4*)&o[0];
        *(float4*)&C[row * ldc + n0 + c1] = *(float4*)&o[4];
    }
}

// ---------------------------------------------------------------------------
// K4b: pooled[b][j] = sum_n P[n*B+b][j]
// ---------------------------------------------------------------------------
__global__ void pool_kernel() {
    size_t idx = (size_t)blockIdx.x * blockDim.x + threadIdx.x;   // over B*256
    float s = 0.f;
#pragma unroll
    for (int n = 0; n < NNODE; ++n)
        s += g_P[(size_t)n * NBATCH * PHI_OUT + idx];
    g_pooled[idx] = s;
}

// ---------------------------------------------------------------------------
// K5b: mean = R@Wm+bm ; log_std = clip(R@Ws+bs). 32 batch rows per CTA.
// thread t: j = t&63 (j<32 -> mean head, else std head), row group t>>6.
// ---------------------------------------------------------------------------
__global__ __launch_bounds__(256)
void heads_kernel(const float* __restrict__ Wm, const float* __restrict__ bm,
                  const float* __restrict__ Ws, const float* __restrict__ bs,
                  float* __restrict__ out) {
    __shared__ float sR[32 * 256];
    const int tid = threadIdx.x;
    const size_t b0 = (size_t)blockIdx.x * 32;

    const float4* src = (const float4*)(g_R + b0 * 256);
    float4* dst = (float4*)sR;
#pragma unroll
    for (int i = 0; i < 8; ++i) dst[tid + i * 256] = src[tid + i * 256];
    __syncthreads();

    const int j  = tid & 63;
    const int rg = tid >> 6;                 // 0..3
    const bool isMean = (j < 32);
    const int jj = j & 31;
    const float* W = isMean ? Wm : Ws;

    float acc[8];
#pragma unroll
    for (int s = 0; s < 8; ++s) acc[s] = 0.f;

#pragma unroll 4
    for (int k = 0; k < 256; ++k) {
        float w = W[k * ACT + jj];
#pragma unroll
        for (int s = 0; s < 8; ++s)
            acc[s] = fmaf(sR[(rg + s * 4) * 256 + k], w, acc[s]);
    }

#pragma unroll
    for (int s = 0; s < 8; ++s) {
        size_t row = b0 + rg + s * 4;
        if (isMean) {
            out[row * ACT + jj] = acc[s] + bm[jj];
        } else {
            float v = acc[s] + bs[jj];
            v = fminf(fmaxf(v, -20.f), 2.f);
            out[(size_t)NBATCH * ACT + row * ACT + jj] = v;
        }
    }
}

// ---------------------------------------------------------------------------
// Host launcher
// ---------------------------------------------------------------------------
extern "C" void kernel_launch(void* const* d_in, const int* in_sizes, int n_in,
                              void* d_out, int out_size) {
    const float* obs  = (const float*)d_in[0];
    const float* ef   = (const float*)d_in[1];
    const int*   eto  = (const int*)  d_in[2];
    const float* iso  = (const float*)d_in[3];
    const float* isof = (const float*)d_in[4];
    const float* W1   = (const float*)d_in[5];
    const float* b1   = (const float*)d_in[6];
    const float* W2   = (const float*)d_in[7];
    const float* b2   = (const float*)d_in[8];
    const float* Wr   = (const float*)d_in[9];
    const float* br   = (const float*)d_in[10];
    const float* Wm   = (const float*)d_in[11];
    const float* bm   = (const float*)d_in[12];
    const float* Ws   = (const float*)d_in[13];
    const float* bs   = (const float*)d_in[14];
    float* out = (float*)d_out;

    // Resolve scratch symbol addresses (host query; graph-capture safe)
    void *pXnf, *pCbody, *pH, *pP, *pPooled, *pR;
    cudaGetSymbolAddress(&pXnf,    g_Xnf);
    cudaGetSymbolAddress(&pCbody,  g_Cbody);
    cudaGetSymbolAddress(&pH,      g_H);
    cudaGetSymbolAddress(&pP,      g_P);
    cudaGetSymbolAddress(&pPooled, g_pooled);
    cudaGetSymbolAddress(&pR,      g_R);

    // K0: segment lists
    seg_kernel<<<1, 32>>>(eto);

    // K1: pack inputs + segment max
    pack_kernel<<<NNODE * NBATCH, 128>>>(obs, ef, iso, isof);

    // K2: C_body = body @ W1[:64,:]   (M=8192, K=64, N=256)
    gemm128_kernel<false, false><<<dim3(2, NBATCH / 128), 256>>>(
        obs, OBS_LD, W1, HID, (float*)pCbody, HID, DBODY,
        nullptr, nullptr, 0);

    // K3: H = relu(Xnf @ W1[64:,:] + C_body[b] + b1)   (M=98304, K=256, N=256)
    gemm128_kernel<true, true><<<dim3(2, NNODE * NBATCH / 128), 256>>>(
        (const float*)pXnf, 256, W1 + (size_t)DBODY * HID, HID, (float*)pH, HID, 256,
        b1, (const float*)pCbody, NBATCH - 1);

    // K4a: P = relu(H @ W2 + b2)   (M=98304, K=256, N=256)
    gemm128_kernel<true, false><<<dim3(2, NNODE * NBATCH / 128), 256>>>(
        (const float*)pH, HID, W2, PHI_OUT, (float*)pP, PHI_OUT, HID,
        b2, nullptr, 0);

    // K4b: pooled = sum_n P_n
    pool_kernel<<<(NBATCH * PHI_OUT) / 256, 256>>>();

    // K5a: R = relu(pooled @ W1_rho + b1_rho)   (M=8192, K=256, N=256)
    gemm128_kernel<true, false><<<dim3(2, NBATCH / 128), 256>>>(
        (const float*)pPooled, PHI_OUT, Wr, HID, (float*)pR, HID, PHI_OUT,
        br, nullptr, 0);

    // K5b: heads
    heads_kernel<<<NBATCH / 32, 256>>>(Wm, bm, Ws, bs, out);
}

// round 8
// speedup vs baseline: 1.6925x; 1.6925x over previous
#include <cuda_runtime.h>
#include <cfloat>
#include <cstdint>
#include <cstdio>

// ---------------------------------------------------------------------------
// Problem constants
// ---------------------------------------------------------------------------
static constexpr int NBATCH   = 8192;
static constexpr int DBODY    = 64;
static constexpr int DOBJ     = 128;
static constexpr int NOBJ     = 9;
static constexpr int NEDGE    = 72;
static constexpr int DEDGE    = 128;
static constexpr int NISO     = 3;
static constexpr int NNODE    = NOBJ + NISO;      // 12
static constexpr int HID      = 256;
static constexpr int PHI_OUT  = 256;
static constexpr int ACT      = 32;
static constexpr int OBS_LD   = DBODY + NOBJ * DOBJ;  // 1216

// ---------------------------------------------------------------------------
// Scratch (device globals -- no dynamic allocation allowed)
// ---------------------------------------------------------------------------
__device__ float g_Xnf[(size_t)NNODE * NBATCH * 256];
__device__ float g_Cbody[(size_t)NBATCH * HID];
__device__ float g_H[(size_t)NNODE * NBATCH * HID];
__device__ float g_P[(size_t)NNODE * NBATCH * PHI_OUT];
__device__ float g_pooled[(size_t)NBATCH * PHI_OUT];
__device__ float g_R[(size_t)NBATCH * HID];
__device__ int   g_seglist[NOBJ * NEDGE];
__device__ int   g_segcnt[NOBJ];

// ---------------------------------------------------------------------------
// K0: build segment lists from edges_to (generic, honors the input array)
// ---------------------------------------------------------------------------
__global__ void seg_kernel(const int* __restrict__ edges_to) {
    if (threadIdx.x == 0 && blockIdx.x == 0) {
        for (int n = 0; n < NOBJ; ++n) {
            int c = 0;
            for (int e = 0; e < NEDGE; ++e)
                if (edges_to[e] == n) g_seglist[n * NEDGE + c++] = e;
            g_segcnt[n] = c;
        }
    }
}

// ---------------------------------------------------------------------------
// K1: segment-max over incoming edges + pack Xnf[n*B+b] = [node(128)|feat(128)]
// ---------------------------------------------------------------------------
__global__ void pack_kernel(const float* __restrict__ obs,
                            const float* __restrict__ edges,
                            const float* __restrict__ iso,
                            const float* __restrict__ isof) {
    int n     = blockIdx.x % NNODE;
    size_t b  = blockIdx.x / NNODE;
    int d     = threadIdx.x;                       // 0..127

    float node, feat;
    if (n < NOBJ) {
        node = obs[b * OBS_LD + DBODY + (size_t)n * DOBJ + d];
        float m = -FLT_MAX;
        int cnt = g_segcnt[n];
        for (int k = 0; k < cnt; ++k) {
            int e = g_seglist[n * NEDGE + k];
            m = fmaxf(m, edges[(b * NEDGE + e) * DEDGE + d]);
        }
        feat = m;
    } else {
        int i = n - NOBJ;
        node = iso [(b * NISO + i) * DOBJ + d];
        feat = isof[(b * NISO + i) * DEDGE + d];
    }
    size_t row = (size_t)n * NBATCH + b;
    g_Xnf[row * 256 + d]       = node;
    g_Xnf[row * 256 + 128 + d] = feat;
}

// ---------------------------------------------------------------------------
// TF32 helpers
// ---------------------------------------------------------------------------
__device__ __forceinline__ float to_tf32(float x) {
    uint32_t u;
    asm("cvt.rna.tf32.f32 %0, %1;" : "=r"(u) : "f"(x));
    return __uint_as_float(u);
}

__device__ __forceinline__ void mma_tf32(float (&c)[4],
                                         const uint32_t (&a)[4],
                                         const uint32_t (&b)[2]) {
    asm volatile(
        "mma.sync.aligned.m16n8k8.row.col.f32.tf32.tf32.f32 "
        "{%0,%1,%2,%3}, {%4,%5,%6,%7}, {%8,%9}, {%0,%1,%2,%3};\n"
        : "+f"(c[0]), "+f"(c[1]), "+f"(c[2]), "+f"(c[3])
        : "r"(a[0]), "r"(a[1]), "r"(a[2]), "r"(a[3]),
          "r"(b[0]), "r"(b[1]));
}

// ---------------------------------------------------------------------------
// TF32 tensor-core GEMM: 128x128 CTA tile, KC=32 chunks, K % 32 == 0.
// 8 warps in 4(m) x 2(n); warp tile 32x64 = 2 m-frags x 8 n-frags m16n8k8.
// C = op(A[M,K] @ B[K,N] (+bias) (+rowadd[(row&rowmask)*256+col]) (relu))
// ---------------------------------------------------------------------------
template<bool RELU, bool ROWADD>
__global__ __launch_bounds__(256)
void gemm_tf32_kernel(const float* __restrict__ A, int lda,
                      const float* __restrict__ Bw, int ldb,
                      float* __restrict__ C, int ldc,
                      int K,
                      const float* __restrict__ bias,
                      const float* __restrict__ rowadd,
                      int rowmask) {
    const int tid  = threadIdx.x;
    const int m0   = blockIdx.y * 128;
    const int n0   = blockIdx.x * 128;
    const int wid  = tid >> 5;
    const int lane = tid & 31;
    const int wm   = wid >> 1;          // 0..3  (m quadrant)
    const int wn   = wid & 1;           // 0..1  (n half)
    const int lr   = lane >> 2;         // 0..7
    const int lc   = lane & 3;          // 0..3

    // smem strides chosen for conflict-free fragment loads:
    //  A: bank = (r*36 + c)%32 = 4r+c  -> injective over (r<8, c<4)
    //  B: bank = (k*136 + n)%32 = 8k+n -> injective over (k<4, n<8)
    __shared__ float sA[128][36];
    __shared__ float sB[32][136];

    float acc[2][8][4];
#pragma unroll
    for (int mf = 0; mf < 2; ++mf)
#pragma unroll
        for (int nf = 0; nf < 8; ++nf)
#pragma unroll
            for (int q = 0; q < 4; ++q) acc[mf][nf][q] = 0.f;

    // global load mapping: 128x32 chunk each for A and B; 4 x float4 / thread
    const int arow = tid >> 3;          // 0..31 (base row, +32*i)
    const int akq  = tid & 7;           // float4 index along k
    const int bkr  = tid >> 5;          // 0..7  (base k, +8*i)
    const int bnq  = tid & 31;          // float4 index along n

    const float* Aptr = A  + (size_t)(m0 + arow) * lda + 4 * akq;
    const float* Bptr = Bw + (size_t)bkr * ldb + n0 + 4 * bnq;

    const int nChunk = K >> 5;
    float4 pa[4], pb[4];
#pragma unroll
    for (int i = 0; i < 4; ++i) pa[i] = *(const float4*)(Aptr + (size_t)i * 32 * lda);
#pragma unroll
    for (int i = 0; i < 4; ++i) pb[i] = *(const float4*)(Bptr + (size_t)i * 8 * ldb);

    for (int t = 0; t < nChunk; ++t) {
        // stage chunk into smem with tf32 rounding
#pragma unroll
        for (int i = 0; i < 4; ++i) {
            float4 v = pa[i];
            float4 w = make_float4(to_tf32(v.x), to_tf32(v.y), to_tf32(v.z), to_tf32(v.w));
            *(float4*)&sA[arow + i * 32][4 * akq] = w;
        }
#pragma unroll
        for (int i = 0; i < 4; ++i) {
            float4 v = pb[i];
            float4 w = make_float4(to_tf32(v.x), to_tf32(v.y), to_tf32(v.z), to_tf32(v.w));
            *(float4*)&sB[bkr + i * 8][4 * bnq] = w;
        }
        __syncthreads();

        if (t + 1 < nChunk) {
#pragma unroll
            for (int i = 0; i < 4; ++i)
                pa[i] = *(const float4*)(Aptr + (size_t)(t + 1) * 32 + (size_t)i * 32 * lda);
#pragma unroll
            for (int i = 0; i < 4; ++i)
                pb[i] = *(const float4*)(Bptr + (size_t)((t + 1) * 32 + i * 8) * ldb);
        }

#pragma unroll
        for (int ks = 0; ks < 4; ++ks) {
            const int k0 = ks * 8;
            uint32_t a[2][4];
#pragma unroll
            for (int mf = 0; mf < 2; ++mf) {
                const float* p = &sA[wm * 32 + mf * 16 + lr][k0 + lc];
                a[mf][0] = __float_as_uint(p[0]);
                a[mf][1] = __float_as_uint(p[8 * 36]);
                a[mf][2] = __float_as_uint(p[4]);
                a[mf][3] = __float_as_uint(p[8 * 36 + 4]);
            }
            uint32_t b[8][2];
#pragma unroll
            for (int nf = 0; nf < 8; ++nf) {
                const float* p = &sB[k0 + lc][wn * 64 + nf * 8 + lr];
                b[nf][0] = __float_as_uint(p[0]);
                b[nf][1] = __float_as_uint(p[4 * 136]);
            }
#pragma unroll
            for (int mf = 0; mf < 2; ++mf)
#pragma unroll
                for (int nf = 0; nf < 8; ++nf)
                    mma_tf32(acc[mf][nf], a[mf], b[nf]);
        }
        __syncthreads();
    }

    // epilogue: c0,c1 at (row, 2*lc + {0,1}); c2,c3 at (row+8, ...)
    const int r_base = m0 + wm * 32 + lr;
    const int c_base = n0 + wn * 64 + 2 * lc;
#pragma unroll
    for (int mf = 0; mf < 2; ++mf) {
#pragma unroll
        for (int half = 0; half < 2; ++half) {
            const int row = r_base + mf * 16 + half * 8;
            const float* rp = nullptr;
            if (ROWADD) rp = rowadd + ((size_t)(row & rowmask) << 8);
#pragma unroll
            for (int nf = 0; nf < 8; ++nf) {
                const int col = c_base + nf * 8;
                float v0 = acc[mf][nf][half * 2 + 0];
                float v1 = acc[mf][nf][half * 2 + 1];
                if (bias) {
                    float2 bv = *(const float2*)&bias[col];
                    v0 += bv.x; v1 += bv.y;
                }
                if (ROWADD) {
                    float2 av = *(const float2*)&rp[col];
                    v0 += av.x; v1 += av.y;
                }
                if (RELU) { v0 = fmaxf(v0, 0.f); v1 = fmaxf(v1, 0.f); }
                *(float2*)&C[(size_t)row * ldc + col] = make_float2(v0, v1);
            }
        }
    }
}

// ---------------------------------------------------------------------------
// K4b: pooled[b][j] = sum_n P[n*B+b][j]
// ---------------------------------------------------------------------------
__global__ void pool_kernel() {
    size_t idx = (size_t)blockIdx.x * blockDim.x + threadIdx.x;
    float s = 0.f;
#pragma unroll
    for (int n = 0; n < NNODE; ++n)
        s += g_P[(size_t)n * NBATCH * PHI_OUT + idx];
    g_pooled[idx] = s;
}

// ---------------------------------------------------------------------------
// K5b: mean = R@Wm+bm ; log_std = clip(R@Ws+bs). 32 batch rows per CTA.
// ---------------------------------------------------------------------------
__global__ __launch_bounds__(256)
void heads_kernel(const float* __restrict__ Wm, const float* __restrict__ bm,
                  const float* __restrict__ Ws, const float* __restrict__ bs,
                  float* __restrict__ out) {
    __shared__ float sR[32 * 256];
    const int tid = threadIdx.x;
    const size_t b0 = (size_t)blockIdx.x * 32;

    const float4* src = (const float4*)(g_R + b0 * 256);
    float4* dst = (float4*)sR;
#pragma unroll
    for (int i = 0; i < 8; ++i) dst[tid + i * 256] = src[tid + i * 256];
    __syncthreads();

    const int j  = tid & 63;
    const int rg = tid >> 6;
    const bool isMean = (j < 32);
    const int jj = j & 31;
    const float* W = isMean ? Wm : Ws;

    float acc[8];
#pragma unroll
    for (int s = 0; s < 8; ++s) acc[s] = 0.f;

#pragma unroll 4
    for (int k = 0; k < 256; ++k) {
        float w = W[k * ACT + jj];
#pragma unroll
        for (int s = 0; s < 8; ++s)
            acc[s] = fmaf(sR[(rg + s * 4) * 256 + k], w, acc[s]);
    }

#pragma unroll
    for (int s = 0; s < 8; ++s) {
        size_t row = b0 + rg + s * 4;
        if (isMean) {
            out[row * ACT + jj] = acc[s] + bm[jj];
        } else {
            float v = acc[s] + bs[jj];
            v = fminf(fmaxf(v, -20.f), 2.f);
            out[(size_t)NBATCH * ACT + row * ACT + jj] = v;
        }
    }
}

// ---------------------------------------------------------------------------
// Host launcher
// ---------------------------------------------------------------------------
extern "C" void kernel_launch(void* const* d_in, const int* in_sizes, int n_in,
                              void* d_out, int out_size) {
    const float* obs  = (const float*)d_in[0];
    const float* ef   = (const float*)d_in[1];
    const int*   eto  = (const int*)  d_in[2];
    const float* iso  = (const float*)d_in[3];
    const float* isof = (const float*)d_in[4];
    const float* W1   = (const float*)d_in[5];
    const float* b1   = (const float*)d_in[6];
    const float* W2   = (const float*)d_in[7];
    const float* b2   = (const float*)d_in[8];
    const float* Wr   = (const float*)d_in[9];
    const float* br   = (const float*)d_in[10];
    const float* Wm   = (const float*)d_in[11];
    const float* bm   = (const float*)d_in[12];
    const float* Ws   = (const float*)d_in[13];
    const float* bs   = (const float*)d_in[14];
    float* out = (float*)d_out;

    void *pXnf, *pCbody, *pH, *pP, *pPooled, *pR;
    cudaGetSymbolAddress(&pXnf,    g_Xnf);
    cudaGetSymbolAddress(&pCbody,  g_Cbody);
    cudaGetSymbolAddress(&pH,      g_H);
    cudaGetSymbolAddress(&pP,      g_P);
    cudaGetSymbolAddress(&pPooled, g_pooled);
    cudaGetSymbolAddress(&pR,      g_R);

    // K0: segment lists
    seg_kernel<<<1, 32>>>(eto);

    // K1: pack inputs + segment max
    pack_kernel<<<NNODE * NBATCH, 128>>>(obs, ef, iso, isof);

    // K2: C_body = body @ W1[:64,:]   (M=8192, K=64, N=256)
    gemm_tf32_kernel<false, false><<<dim3(2, NBATCH / 128), 256>>>(
        obs, OBS_LD, W1, HID, (float*)pCbody, HID, DBODY,
        nullptr, nullptr, 0);

    // K3: H = relu(Xnf @ W1[64:,:] + C_body[b] + b1)   (M=98304, K=256, N=256)
    gemm_tf32_kernel<true, true><<<dim3(2, NNODE * NBATCH / 128), 256>>>(
        (const float*)pXnf, 256, W1 + (size_t)DBODY * HID, HID, (float*)pH, HID, 256,
        b1, (const float*)pCbody, NBATCH - 1);

    // K4a: P = relu(H @ W2 + b2)   (M=98304, K=256, N=256)
    gemm_tf32_kernel<true, false><<<dim3(2, NNODE * NBATCH / 128), 256>>>(
        (const float*)pH, HID, W2, PHI_OUT, (float*)pP, PHI_OUT, HID,
        b2, nullptr, 0);

    // K4b: pooled = sum_n P_n
    pool_kernel<<<(NBATCH * PHI_OUT) / 256, 256>>>();

    // K5a: R = relu(pooled @ W1_rho + b1_rho)   (M=8192, K=256, N=256)
    gemm_tf32_kernel<true, false><<<dim3(2, NBATCH / 128), 256>>>(
        (const float*)pPooled, PHI_OUT, Wr, HID, (float*)pR, HID, PHI_OUT,
        br, nullptr, 0);

    // K5b: heads
    heads_kernel<<<NBATCH / 32, 256>>>(Wm, bm, Ws, bs, out);
}

// round 10
// speedup vs baseline: 1.8671x; 1.1031x over previous
#include <cuda_runtime.h>
#include <cfloat>
#include <cstdint>
#include <cstdio>

// ---------------------------------------------------------------------------
// Problem constants
// ---------------------------------------------------------------------------
static constexpr int NBATCH   = 8192;
static constexpr int DBODY    = 64;
static constexpr int DOBJ     = 128;
static constexpr int NOBJ     = 9;
static constexpr int NEDGE    = 72;
static constexpr int DEDGE    = 128;
static constexpr int NISO     = 3;
static constexpr int NNODE    = NOBJ + NISO;      // 12
static constexpr int HID      = 256;
static constexpr int PHI_OUT  = 256;
static constexpr int ACT      = 32;
static constexpr int OBS_LD   = DBODY + NOBJ * DOBJ;  // 1216

// ---------------------------------------------------------------------------
// Scratch (device globals -- no dynamic allocation allowed)
// ---------------------------------------------------------------------------
__device__ float g_Xnf[(size_t)NNODE * NBATCH * 256];
__device__ float g_Cbody[(size_t)NBATCH * HID];
__device__ float g_H[(size_t)NNODE * NBATCH * HID];
__device__ float g_P[(size_t)NNODE * NBATCH * PHI_OUT];
__device__ float g_pooled[(size_t)NBATCH * PHI_OUT];
__device__ float g_R[(size_t)NBATCH * HID];
__device__ int   g_seglist[NOBJ * NEDGE];
__device__ int   g_segcnt[NOBJ];
// tf32-rounded weight copies (so the GEMM can cp.async raw bytes)
__device__ float g_W1r[(DBODY + 256) * HID];   // 320 x 256
__device__ float g_W2r[HID * PHI_OUT];
__device__ float g_Wrr[PHI_OUT * HID];

// ---------------------------------------------------------------------------
// TF32 helpers
// ---------------------------------------------------------------------------
__device__ __forceinline__ float to_tf32(float x) {
    uint32_t u;
    asm("cvt.rna.tf32.f32 %0, %1;" : "=r"(u) : "f"(x));
    return __uint_as_float(u);
}

__device__ __forceinline__ void mma_tf32(float (&c)[4],
                                         const uint32_t (&a)[4],
                                         const uint32_t (&b)[2]) {
    asm volatile(
        "mma.sync.aligned.m16n8k8.row.col.f32.tf32.tf32.f32 "
        "{%0,%1,%2,%3}, {%4,%5,%6,%7}, {%8,%9}, {%0,%1,%2,%3};\n"
        : "+f"(c[0]), "+f"(c[1]), "+f"(c[2]), "+f"(c[3])
        : "r"(a[0]), "r"(a[1]), "r"(a[2]), "r"(a[3]),
          "r"(b[0]), "r"(b[1]));
}

__device__ __forceinline__ void cp16(uint32_t saddr, const void* g) {
    asm volatile("cp.async.ca.shared.global [%0], [%1], 16;\n"
                 :: "r"(saddr), "l"(g));
}

// ---------------------------------------------------------------------------
// K-1: pre-round weights to tf32 (rna) once per call
// ---------------------------------------------------------------------------
__global__ void prep_kernel(const float* __restrict__ W1,
                            const float* __restrict__ W2,
                            const float* __restrict__ Wr) {
    int i = blockIdx.x * 256 + threadIdx.x;
    if (i < (DBODY + 256) * HID) g_W1r[i] = to_tf32(W1[i]);
    if (i < HID * PHI_OUT) {
        g_W2r[i] = to_tf32(W2[i]);
        g_Wrr[i] = to_tf32(Wr[i]);
    }
}

// ---------------------------------------------------------------------------
// K0: build segment lists from edges_to (generic, honors the input array)
// ---------------------------------------------------------------------------
__global__ void seg_kernel(const int* __restrict__ edges_to) {
    if (threadIdx.x == 0 && blockIdx.x == 0) {
        for (int n = 0; n < NOBJ; ++n) {
            int c = 0;
            for (int e = 0; e < NEDGE; ++e)
                if (edges_to[e] == n) g_seglist[n * NEDGE + c++] = e;
            g_segcnt[n] = c;
        }
    }
}

// ---------------------------------------------------------------------------
// K1: segment-max + pack, outputs rounded to tf32 (they feed the MMA as A)
// ---------------------------------------------------------------------------
__global__ void pack_kernel(const float* __restrict__ obs,
                            const float* __restrict__ edges,
                            const float* __restrict__ iso,
                            const float* __restrict__ isof) {
    int n     = blockIdx.x % NNODE;
    size_t b  = blockIdx.x / NNODE;
    int d     = threadIdx.x;                       // 0..127

    float node, feat;
    if (n < NOBJ) {
        node = obs[b * OBS_LD + DBODY + (size_t)n * DOBJ + d];
        float m = -FLT_MAX;
        int cnt = g_segcnt[n];
        for (int k = 0; k < cnt; ++k) {
            int e = g_seglist[n * NEDGE + k];
            m = fmaxf(m, edges[(b * NEDGE + e) * DEDGE + d]);
        }
        feat = m;
    } else {
        int i = n - NOBJ;
        node = iso [(b * NISO + i) * DOBJ + d];
        feat = isof[(b * NISO + i) * DEDGE + d];
    }
    size_t row = (size_t)n * NBATCH + b;
    g_Xnf[row * 256 + d]       = to_tf32(node);
    g_Xnf[row * 256 + 128 + d] = to_tf32(feat);
}

// ---------------------------------------------------------------------------
// TF32 tensor-core GEMM, 256x128 CTA tile, KC=32, cp.async double-buffered.
// 8 warps in 4(m) x 2(n); warp tile 64x64 = 4 m-frags x 8 n-frags m16n8k8.
// Inputs A,B must already be tf32-rounded. K % 32 == 0, M % 256 == 0.
// smem (dynamic): sA[2][256][36] + sB[2][32][136]  = 108544 B
// ---------------------------------------------------------------------------
static constexpr int SA_STRIDE = 36;
static constexpr int SB_STRIDE = 136;
static constexpr int SA_BUF    = 256 * SA_STRIDE;          // floats per buffer
static constexpr int SB_BUF    = 32 * SB_STRIDE;
static constexpr size_t GEMM_SMEM = (size_t)(2 * SA_BUF + 2 * SB_BUF) * 4;

template<bool RELU, bool ROWADD, bool ROUND_OUT>
__global__ __launch_bounds__(256, 1)
void gemm_tf32_db(const float* __restrict__ A, int lda,
                  const float* __restrict__ Bw, int ldb,
                  float* __restrict__ C, int ldc,
                  int K,
                  const float* __restrict__ bias,
                  const float* __restrict__ rowadd,
                  int rowmask) {
    extern __shared__ float smem[];
    float* sA = smem;                    // [2][256][36]
    float* sB = smem + 2 * SA_BUF;       // [2][32][136]

    const int tid  = threadIdx.x;
    const int m0   = blockIdx.y * 256;
    const int n0   = blockIdx.x * 128;
    const int wid  = tid >> 5;
    const int lane = tid & 31;
    const int wm   = wid >> 1;          // 0..3  (64-row band)
    const int wn   = wid & 1;           // 0..1  (64-col half)
    const int lr   = lane >> 2;         // 0..7
    const int lc   = lane & 3;          // 0..3

    float acc[4][8][4];
#pragma unroll
    for (int mf = 0; mf < 4; ++mf)
#pragma unroll
        for (int nf = 0; nf < 8; ++nf)
#pragma unroll
            for (int q = 0; q < 4; ++q) acc[mf][nf][q] = 0.f;

    // global->smem mapping: A chunk 256x32 (8 x 16B/thread), B chunk 32x128 (4 x 16B/thread)
    const int arow = tid >> 3;          // 0..31 (+32*i)
    const int akq  = tid & 7;           // float4 slot along k
    const int bkr  = tid >> 5;          // 0..7  (+8*i)
    const int bnq  = tid & 31;          // float4 slot along n

    const float* Ag = A  + (size_t)(m0 + arow) * lda + 4 * akq;
    const float* Bg = Bw + (size_t)bkr * ldb + n0 + 4 * bnq;

    const uint32_t sA_addr = (uint32_t)__cvta_generic_to_shared(sA)
                           + ((arow * SA_STRIDE + 4 * akq) << 2);
    const uint32_t sB_addr = (uint32_t)__cvta_generic_to_shared(sB)
                           + ((bkr * SB_STRIDE + 4 * bnq) << 2);

    const int nChunk = K >> 5;

    auto issue = [&](int t, int buf) {
        const float* ap = Ag + (size_t)t * 32;
        uint32_t sa = sA_addr + buf * (SA_BUF << 2);
#pragma unroll
        for (int i = 0; i < 8; ++i)
            cp16(sa + ((i * 32 * SA_STRIDE) << 2), ap + (size_t)i * 32 * lda);
        const float* bp = Bg + (size_t)t * 32 * ldb;
        uint32_t sb = sB_addr + buf * (SB_BUF << 2);
#pragma unroll
        for (int i = 0; i < 4; ++i)
            cp16(sb + ((i * 8 * SB_STRIDE) << 2), bp + (size_t)i * 8 * ldb);
        asm volatile("cp.async.commit_group;\n");
    };

    issue(0, 0);

    for (int t = 0; t < nChunk; ++t) {
        if (t + 1 < nChunk) {
            issue(t + 1, (t + 1) & 1);
            asm volatile("cp.async.wait_group 1;\n");
        } else {
            asm volatile("cp.async.wait_group 0;\n");
        }
        __syncthreads();

        const float* bufA = sA + (t & 1) * SA_BUF;
        const float* bufB = sB + (t & 1) * SB_BUF;

#pragma unroll
        for (int ks = 0; ks < 4; ++ks) {
            const int k0 = ks * 8;
            uint32_t a[4][4];
#pragma unroll
            for (int mf = 0; mf < 4; ++mf) {
                const float* p = bufA + (wm * 64 + mf * 16 + lr) * SA_STRIDE + k0 + lc;
                a[mf][0] = __float_as_uint(p[0]);
                a[mf][1] = __float_as_uint(p[8 * SA_STRIDE]);
                a[mf][2] = __float_as_uint(p[4]);
                a[mf][3] = __float_as_uint(p[8 * SA_STRIDE + 4]);
            }
            uint32_t b[8][2];
#pragma unroll
            for (int nf = 0; nf < 8; ++nf) {
                const float* p = bufB + (k0 + lc) * SB_STRIDE + wn * 64 + nf * 8 + lr;
                b[nf][0] = __float_as_uint(p[0]);
                b[nf][1] = __float_as_uint(p[4 * SB_STRIDE]);
            }
#pragma unroll
            for (int mf = 0; mf < 4; ++mf)
#pragma unroll
                for (int nf = 0; nf < 8; ++nf)
                    mma_tf32(acc[mf][nf], a[mf], b[nf]);
        }
        __syncthreads();
    }

    // epilogue
    const int r_base = m0 + wm * 64 + lr;
    const int c_base = n0 + wn * 64 + 2 * lc;
#pragma unroll
    for (int mf = 0; mf < 4; ++mf) {
#pragma unroll
        for (int half = 0; half < 2; ++half) {
            const int row = r_base + mf * 16 + half * 8;
            const float* rp = nullptr;
            if (ROWADD) rp = rowadd + ((size_t)(row & rowmask) << 8);
#pragma unroll
            for (int nf = 0; nf < 8; ++nf) {
                const int col = c_base + nf * 8;
                float v0 = acc[mf][nf][half * 2 + 0];
                float v1 = acc[mf][nf][half * 2 + 1];
                if (bias) {
                    float2 bv = *(const float2*)&bias[col];
                    v0 += bv.x; v1 += bv.y;
                }
                if (ROWADD) {
                    float2 av = *(const float2*)&rp[col];
                    v0 += av.x; v1 += av.y;
                }
                if (RELU) { v0 = fmaxf(v0, 0.f); v1 = fmaxf(v1, 0.f); }
                if (ROUND_OUT) { v0 = to_tf32(v0); v1 = to_tf32(v1); }
                *(float2*)&C[(size_t)row * ldc + col] = make_float2(v0, v1);
            }
        }
    }
}

// ---------------------------------------------------------------------------
// K4b: pooled[b][j] = sum_n P[n*B+b][j], rounded (feeds K5a's MMA as A)
// ---------------------------------------------------------------------------
__global__ void pool_kernel() {
    size_t idx = (size_t)blockIdx.x * blockDim.x + threadIdx.x;
    float s = 0.f;
#pragma unroll
    for (int n = 0; n < NNODE; ++n)
        s += g_P[(size_t)n * NBATCH * PHI_OUT + idx];
    g_pooled[idx] = to_tf32(s);
}

// ---------------------------------------------------------------------------
// K5b: mean = R@Wm+bm ; log_std = clip(R@Ws+bs). 32 batch rows per CTA.
// ---------------------------------------------------------------------------
__global__ __launch_bounds__(256)
void heads_kernel(const float* __restrict__ Wm, const float* __restrict__ bm,
                  const float* __restrict__ Ws, const float* __restrict__ bs,
                  float* __restrict__ out) {
    __shared__ float sR[32 * 256];
    const int tid = threadIdx.x;
    const size_t b0 = (size_t)blockIdx.x * 32;

    const float4* src = (const float4*)(g_R + b0 * 256);
    float4* dst = (float4*)sR;
#pragma unroll
    for (int i = 0; i < 8; ++i) dst[tid + i * 256] = src[tid + i * 256];
    __syncthreads();

    const int j  = tid & 63;
    const int rg = tid >> 6;
    const bool isMean = (j < 32);
    const int jj = j & 31;
    const float* W = isMean ? Wm : Ws;

    float acc[8];
#pragma unroll
    for (int s = 0; s < 8; ++s) acc[s] = 0.f;

#pragma unroll 4
    for (int k = 0; k < 256; ++k) {
        float w = W[k * ACT + jj];
#pragma unroll
        for (int s = 0; s < 8; ++s)
            acc[s] = fmaf(sR[(rg + s * 4) * 256 + k], w, acc[s]);
    }

#pragma unroll
    for (int s = 0; s < 8; ++s) {
        size_t row = b0 + rg + s * 4;
        if (isMean) {
            out[row * ACT + jj] = acc[s] + bm[jj];
        } else {
            float v = acc[s] + bs[jj];
            v = fminf(fmaxf(v, -20.f), 2.f);
            out[(size_t)NBATCH * ACT + row * ACT + jj] = v;
        }
    }
}

// ---------------------------------------------------------------------------
// Host launcher
// ---------------------------------------------------------------------------
extern "C" void kernel_launch(void* const* d_in, const int* in_sizes, int n_in,
                              void* d_out, int out_size) {
    const float* obs  = (const float*)d_in[0];
    const float* ef   = (const float*)d_in[1];
    const int*   eto  = (const int*)  d_in[2];
    const float* iso  = (const float*)d_in[3];
    const float* isof = (const float*)d_in[4];
    const float* W1   = (const float*)d_in[5];
    const float* b1   = (const float*)d_in[6];
    const float* W2   = (const float*)d_in[7];
    const float* b2   = (const float*)d_in[8];
    const float* Wr   = (const float*)d_in[9];
    const float* br   = (const float*)d_in[10];
    const float* Wm   = (const float*)d_in[11];
    const float* bm   = (const float*)d_in[12];
    const float* Ws   = (const float*)d_in[13];
    const float* bs   = (const float*)d_in[14];
    float* out = (float*)d_out;

    void *pXnf, *pCbody, *pH, *pP, *pPooled, *pR, *pW1r, *pW2r, *pWrr;
    cudaGetSymbolAddress(&pXnf,    g_Xnf);
    cudaGetSymbolAddress(&pCbody,  g_Cbody);
    cudaGetSymbolAddress(&pH,      g_H);
    cudaGetSymbolAddress(&pP,      g_P);
    cudaGetSymbolAddress(&pPooled, g_pooled);
    cudaGetSymbolAddress(&pR,      g_R);
    cudaGetSymbolAddress(&pW1r,    g_W1r);
    cudaGetSymbolAddress(&pW2r,    g_W2r);
    cudaGetSymbolAddress(&pWrr,    g_Wrr);

    // Allow >48KB dynamic smem for each instantiation (idempotent, capture-safe)
    static bool attr_done = false;
    if (!attr_done) {
        cudaFuncSetAttribute(gemm_tf32_db<false, false, false>,
                             cudaFuncAttributeMaxDynamicSharedMemorySize, (int)GEMM_SMEM);
        cudaFuncSetAttribute(gemm_tf32_db<true, true, true>,
                             cudaFuncAttributeMaxDynamicSharedMemorySize, (int)GEMM_SMEM);
        cudaFuncSetAttribute(gemm_tf32_db<true, false, false>,
                             cudaFuncAttributeMaxDynamicSharedMemorySize, (int)GEMM_SMEM);
        attr_done = true;
    }

    // K-1: tf32-round the weights
    prep_kernel<<<(DBODY + 256) * HID / 256, 256>>>(W1, W2, Wr);

    // K0: segment lists
    seg_kernel<<<1, 32>>>(eto);

    // K1: pack inputs + segment max (tf32-rounded outputs)
    pack_kernel<<<NNODE * NBATCH, 128>>>(obs, ef, iso, isof);

    // K2: C_body = body @ W1r[:64,:]   (M=8192, K=64, N=256) -- A truncated to tf32 by HW
    gemm_tf32_db<false, false, false><<<dim3(2, NBATCH / 256), 256, GEMM_SMEM>>>(
        obs, OBS_LD, (const float*)pW1r, HID, (float*)pCbody, HID, DBODY,
        nullptr, nullptr, 0);

    // K3: H = tf32(relu(Xnf @ W1r[64:,:] + C_body[b] + b1))   (M=98304, K=256, N=256)
    gemm_tf32_db<true, true, true><<<dim3(2, NNODE * NBATCH / 256), 256, GEMM_SMEM>>>(
        (const float*)pXnf, 256, (const float*)pW1r + (size_t)DBODY * HID, HID,
        (float*)pH, HID, 256, b1, (const float*)pCbody, NBATCH - 1);

    // K4a: P = relu(H @ W2r + b2)   (M=98304, K=256, N=256)
    gemm_tf32_db<true, false, false><<<dim3(2, NNODE * NBATCH / 256), 256, GEMM_SMEM>>>(
        (const float*)pH, HID, (const float*)pW2r, PHI_OUT, (float*)pP, PHI_OUT, HID,
        b2, nullptr, 0);

    // K4b: pooled = tf32(sum_n P_n)
    pool_kernel<<<(NBATCH * PHI_OUT) / 256, 256>>>();

    // K5a: R = relu(pooled @ Wrr + b1_rho)   (M=8192, K=256, N=256)
    gemm_tf32_db<true, false, false><<<dim3(2, NBATCH / 256), 256, GEMM_SMEM>>>(
        (const float*)pPooled, PHI_OUT, (const float*)pWrr, HID, (float*)pR, HID, PHI_OUT,
        br, nullptr, 0);

    // K5b: heads
    heads_kernel<<<NBATCH / 32, 256>>>(Wm, bm, Ws, bs, out);
}

// round 15
// speedup vs baseline: 1.9497x; 1.0442x over previous
#include <cuda_runtime.h>
#include <cfloat>
#include <cstdint>
#include <cstdio>

// ---------------------------------------------------------------------------
// Problem constants
// ---------------------------------------------------------------------------
static constexpr int NBATCH   = 8192;
static constexpr int DBODY    = 64;
static constexpr int DOBJ     = 128;
static constexpr int NOBJ     = 9;
static constexpr int NEDGE    = 72;
static constexpr int DEDGE    = 128;
static constexpr int NISO     = 3;
static constexpr int NNODE    = NOBJ + NISO;      // 12
static constexpr int HID      = 256;
static constexpr int PHI_OUT  = 256;
static constexpr int ACT      = 32;
static constexpr int OBS_LD   = DBODY + NOBJ * DOBJ;  // 1216

// ---------------------------------------------------------------------------
// Scratch (device globals -- no dynamic allocation allowed)
// ---------------------------------------------------------------------------
__device__ float g_Xnf[(size_t)NNODE * NBATCH * 256];
__device__ float g_Cbody[(size_t)NBATCH * HID];
__device__ float g_H[(size_t)NNODE * NBATCH * HID];
__device__ float g_P[(size_t)NNODE * NBATCH * PHI_OUT];
__device__ float g_pooled[(size_t)NBATCH * PHI_OUT];
__device__ float g_R[(size_t)NBATCH * HID];
__device__ int   g_seglist[NOBJ * NEDGE];
__device__ int   g_segcnt[NOBJ];
// tf32-rounded weight copies (GEMM cp.asyncs raw bytes, no in-loop cvt)
__device__ float g_W1r[(DBODY + 256) * HID];   // 320 x 256
__device__ float g_W2r[HID * PHI_OUT];
__device__ float g_Wrr[PHI_OUT * HID];

// ---------------------------------------------------------------------------
// TF32 helpers
// ---------------------------------------------------------------------------
__device__ __forceinline__ float to_tf32(float x) {
    uint32_t u;
    asm("cvt.rna.tf32.f32 %0, %1;" : "=r"(u) : "f"(x));
    return __uint_as_float(u);
}

__device__ __forceinline__ void mma_tf32(float (&c)[4],
                                         const uint32_t (&a)[4],
                                         const uint32_t (&b)[2]) {
    asm volatile(
        "mma.sync.aligned.m16n8k8.row.col.f32.tf32.tf32.f32 "
        "{%0,%1,%2,%3}, {%4,%5,%6,%7}, {%8,%9}, {%0,%1,%2,%3};\n"
        : "+f"(c[0]), "+f"(c[1]), "+f"(c[2]), "+f"(c[3])
        : "r"(a[0]), "r"(a[1]), "r"(a[2]), "r"(a[3]),
          "r"(b[0]), "r"(b[1]));
}

__device__ __forceinline__ void cp16(uint32_t saddr, const void* g) {
    asm volatile("cp.async.ca.shared.global [%0], [%1], 16;\n"
                 :: "r"(saddr), "l"(g));
}

// ---------------------------------------------------------------------------
// K-1: pre-round weights to tf32 (rna) once per call
// ---------------------------------------------------------------------------
__global__ void prep_kernel(const float* __restrict__ W1,
                            const float* __restrict__ W2,
                            const float* __restrict__ Wr) {
    int i = blockIdx.x * 256 + threadIdx.x;
    if (i < (DBODY + 256) * HID) g_W1r[i] = to_tf32(W1[i]);
    if (i < HID * PHI_OUT) {
        g_W2r[i] = to_tf32(W2[i]);
        g_Wrr[i] = to_tf32(Wr[i]);
    }
}

// ---------------------------------------------------------------------------
// K0: build segment lists from edges_to (generic, honors the input array)
// ---------------------------------------------------------------------------
__global__ void seg_kernel(const int* __restrict__ edges_to) {
    if (threadIdx.x == 0 && blockIdx.x == 0) {
        for (int n = 0; n < NOBJ; ++n) {
            int c = 0;
            for (int e = 0; e < NEDGE; ++e)
                if (edges_to[e] == n) g_seglist[n * NEDGE + c++] = e;
            g_segcnt[n] = c;
        }
    }
}

// ---------------------------------------------------------------------------
// K1: segment-max + pack, outputs rounded to tf32 (feed MMA as A)
// ---------------------------------------------------------------------------
__global__ void pack_kernel(const float* __restrict__ obs,
                            const float* __restrict__ edges,
                            const float* __restrict__ iso,
                            const float* __restrict__ isof) {
    int n     = blockIdx.x % NNODE;
    size_t b  = blockIdx.x / NNODE;
    int d     = threadIdx.x;                       // 0..127

    float node, feat;
    if (n < NOBJ) {
        node = obs[b * OBS_LD + DBODY + (size_t)n * DOBJ + d];
        float m = -FLT_MAX;
        int cnt = g_segcnt[n];
        for (int k = 0; k < cnt; ++k) {
            int e = g_seglist[n * NEDGE + k];
            m = fmaxf(m, edges[(b * NEDGE + e) * DEDGE + d]);
        }
        feat = m;
    } else {
        int i = n - NOBJ;
        node = iso [(b * NISO + i) * DOBJ + d];
        feat = isof[(b * NISO + i) * DEDGE + d];
    }
    size_t row = (size_t)n * NBATCH + b;
    g_Xnf[row * 256 + d]       = to_tf32(node);
    g_Xnf[row * 256 + 128 + d] = to_tf32(feat);
}

// ---------------------------------------------------------------------------
// TF32 mma.sync GEMM, 128x128 CTA tile, KC=32, cp.async double-buffered,
// __launch_bounds__(256,2) to force <=128 regs -> 2 CTAs / 16 warps per SM.
// 8 warps in 4(m) x 2(n); warp tile 32x64 = 2 m-frags x 8 n-frags m16n8k8.
// A,B must be tf32-pre-rounded. K % 32 == 0, M % 128 == 0, N tile = 128.
// smem (dynamic): sA[2][128][36] + sB[2][32][136] = 71680 B
// ---------------------------------------------------------------------------
static constexpr int SA_STRIDE = 36;
static constexpr int SB_STRIDE = 136;
static constexpr int SA_BUF    = 128 * SA_STRIDE;   // floats per buffer
static constexpr int SB_BUF    = 32 * SB_STRIDE;
static constexpr size_t GEMM_SMEM = (size_t)(2 * SA_BUF + 2 * SB_BUF) * 4;

template<bool RELU, bool ROWADD, bool ROUND_OUT>
__global__ __launch_bounds__(256, 2)
void gemm_tf32_db(const float* __restrict__ A, int lda,
                  const float* __restrict__ Bw, int ldb,
                  float* __restrict__ C, int ldc,
                  int K,
                  const float* __restrict__ bias,
                  const float* __restrict__ rowadd,
                  int rowmask) {
    extern __shared__ float smem[];
    float* sA = smem;                    // [2][128][36]
    float* sB = smem + 2 * SA_BUF;       // [2][32][136]

    const int tid  = threadIdx.x;
    const int m0   = blockIdx.y * 128;
    const int n0   = blockIdx.x * 128;
    const int wid  = tid >> 5;
    const int lane = tid & 31;
    const int wm   = wid >> 1;          // 0..3  (32-row band)
    const int wn   = wid & 1;           // 0..1  (64-col half)
    const int lr   = lane >> 2;         // 0..7
    const int lc   = lane & 3;          // 0..3

    float acc[2][8][4];
#pragma unroll
    for (int mf = 0; mf < 2; ++mf)
#pragma unroll
        for (int nf = 0; nf < 8; ++nf)
#pragma unroll
            for (int q = 0; q < 4; ++q) acc[mf][nf][q] = 0.f;

    const uint32_t sA0 = (uint32_t)__cvta_generic_to_shared(sA);
    const uint32_t sB0 = (uint32_t)__cvta_generic_to_shared(sB);
    const int nChunk = K >> 5;

    // staging: A chunk 128x32 and B chunk 32x128, 4 x 16B each per thread
    auto issue = [&](int t, int buf) {
        const uint32_t sa = sA0 + ((uint32_t)buf * SA_BUF << 2);
        const uint32_t sb = sB0 + ((uint32_t)buf * SB_BUF << 2);
#pragma unroll
        for (int i = 0; i < 4; ++i) {
            int s = tid + 256 * i;
            int r = s >> 3, q = s & 7;       // A: row r, k-slot q
            cp16(sa + (uint32_t)((r * SA_STRIDE + 4 * q) << 2),
                 A + (size_t)(m0 + r) * lda + t * 32 + 4 * q);
            int kr = s >> 5, nq = s & 31;    // B: k-row kr, n-slot nq
            cp16(sb + (uint32_t)((kr * SB_STRIDE + 4 * nq) << 2),
                 Bw + (size_t)(t * 32 + kr) * ldb + n0 + 4 * nq);
        }
        asm volatile("cp.async.commit_group;\n");
    };

    issue(0, 0);

    for (int t = 0; t < nChunk; ++t) {
        if (t + 1 < nChunk) {
            issue(t + 1, (t + 1) & 1);
            asm volatile("cp.async.wait_group 1;\n");
        } else {
            asm volatile("cp.async.wait_group 0;\n");
        }
        __syncthreads();

        const float* bufA = sA + (t & 1) * SA_BUF;
        const float* bufB = sB + (t & 1) * SB_BUF;

#pragma unroll
        for (int ks = 0; ks < 4; ++ks) {
            const int k0 = ks * 8;
            uint32_t a[2][4];
#pragma unroll
            for (int mf = 0; mf < 2; ++mf) {
                const float* p = bufA + (wm * 32 + mf * 16 + lr) * SA_STRIDE + k0 + lc;
                a[mf][0] = __float_as_uint(p[0]);
                a[mf][1] = __float_as_uint(p[8 * SA_STRIDE]);
                a[mf][2] = __float_as_uint(p[4]);
                a[mf][3] = __float_as_uint(p[8 * SA_STRIDE + 4]);
            }
            uint32_t b[8][2];
#pragma unroll
            for (int nf = 0; nf < 8; ++nf) {
                const float* p = bufB + (k0 + lc) * SB_STRIDE + wn * 64 + nf * 8 + lr;
                b[nf][0] = __float_as_uint(p[0]);
                b[nf][1] = __float_as_uint(p[4 * SB_STRIDE]);
            }
#pragma unroll
            for (int mf = 0; mf < 2; ++mf)
#pragma unroll
                for (int nf = 0; nf < 8; ++nf)
                    mma_tf32(acc[mf][nf], a[mf], b[nf]);
        }
        __syncthreads();
    }

    // epilogue
    const int r_base = m0 + wm * 32 + lr;
    const int c_base = n0 + wn * 64 + 2 * lc;
#pragma unroll
    for (int mf = 0; mf < 2; ++mf) {
#pragma unroll
        for (int half = 0; half < 2; ++half) {
            const int row = r_base + mf * 16 + half * 8;
            const float* rp = nullptr;
            if (ROWADD) rp = rowadd + ((size_t)(row & rowmask) << 8);
#pragma unroll
            for (int nf = 0; nf < 8; ++nf) {
                const int col = c_base + nf * 8;
                float v0 = acc[mf][nf][half * 2 + 0];
                float v1 = acc[mf][nf][half * 2 + 1];
                if (bias) {
                    float2 bv = *(const float2*)&bias[col];
                    v0 += bv.x; v1 += bv.y;
                }
                if (ROWADD) {
                    float2 av = *(const float2*)&rp[col];
                    v0 += av.x; v1 += av.y;
                }
                if (RELU) { v0 = fmaxf(v0, 0.f); v1 = fmaxf(v1, 0.f); }
                if (ROUND_OUT) { v0 = to_tf32(v0); v1 = to_tf32(v1); }
                *(float2*)&C[(size_t)row * ldc + col] = make_float2(v0, v1);
            }
        }
    }
}

// ---------------------------------------------------------------------------
// K4b: pooled[b][j] = tf32(sum_n P[n*B+b][j])
// ---------------------------------------------------------------------------
__global__ void pool_kernel() {
    size_t idx = (size_t)blockIdx.x * blockDim.x + threadIdx.x;
    float s = 0.f;
#pragma unroll
    for (int n = 0; n < NNODE; ++n)
        s += g_P[(size_t)n * NBATCH * PHI_OUT + idx];
    g_pooled[idx] = to_tf32(s);
}

// ---------------------------------------------------------------------------
// K5b: mean = R@Wm+bm ; log_std = clip(R@Ws+bs). 32 batch rows per CTA.
// ---------------------------------------------------------------------------
__global__ __launch_bounds__(256)
void heads_kernel(const float* __restrict__ Wm, const float* __restrict__ bm,
                  const float* __restrict__ Ws, const float* __restrict__ bs,
                  float* __restrict__ out) {
    __shared__ float sR[32 * 256];
    const int tid = threadIdx.x;
    const size_t b0 = (size_t)blockIdx.x * 32;

    const float4* src = (const float4*)(g_R + b0 * 256);
    float4* dst = (float4*)sR;
#pragma unroll
    for (int i = 0; i < 8; ++i) dst[tid + i * 256] = src[tid + i * 256];
    __syncthreads();

    const int j  = tid & 63;
    const int rg = tid >> 6;
    const bool isMean = (j < 32);
    const int jj = j & 31;
    const float* W = isMean ? Wm : Ws;

    float acc[8];
#pragma unroll
    for (int s = 0; s < 8; ++s) acc[s] = 0.f;

#pragma unroll 4
    for (int k = 0; k < 256; ++k) {
        float w = W[k * ACT + jj];
#pragma unroll
        for (int s = 0; s < 8; ++s)
            acc[s] = fmaf(sR[(rg + s * 4) * 256 + k], w, acc[s]);
    }

#pragma unroll
    for (int s = 0; s < 8; ++s) {
        size_t row = b0 + rg + s * 4;
        if (isMean) {
            out[row * ACT + jj] = acc[s] + bm[jj];
        } else {
            float v = acc[s] + bs[jj];
            v = fminf(fmaxf(v, -20.f), 2.f);
            out[(size_t)NBATCH * ACT + row * ACT + jj] = v;
        }
    }
}

// ---------------------------------------------------------------------------
// Host launcher
// ---------------------------------------------------------------------------
extern "C" void kernel_launch(void* const* d_in, const int* in_sizes, int n_in,
                              void* d_out, int out_size) {
    const float* obs  = (const float*)d_in[0];
    const float* ef   = (const float*)d_in[1];
    const int*   eto  = (const int*)  d_in[2];
    const float* iso  = (const float*)d_in[3];
    const float* isof = (const float*)d_in[4];
    const float* W1   = (const float*)d_in[5];
    const float* b1   = (const float*)d_in[6];
    const float* W2   = (const float*)d_in[7];
    const float* b2   = (const float*)d_in[8];
    const float* Wr   = (const float*)d_in[9];
    const float* br   = (const float*)d_in[10];
    const float* Wm   = (const float*)d_in[11];
    const float* bm   = (const float*)d_in[12];
    const float* Ws   = (const float*)d_in[13];
    const float* bs   = (const float*)d_in[14];
    float* out = (float*)d_out;

    void *pXnf, *pCbody, *pH, *pP, *pPooled, *pR, *pW1r, *pW2r, *pWrr;
    cudaGetSymbolAddress(&pXnf,    g_Xnf);
    cudaGetSymbolAddress(&pCbody,  g_Cbody);
    cudaGetSymbolAddress(&pH,      g_H);
    cudaGetSymbolAddress(&pP,      g_P);
    cudaGetSymbolAddress(&pPooled, g_pooled);
    cudaGetSymbolAddress(&pR,      g_R);
    cudaGetSymbolAddress(&pW1r,    g_W1r);
    cudaGetSymbolAddress(&pW2r,    g_W2r);
    cudaGetSymbolAddress(&pWrr,    g_Wrr);

    static bool attr_done = false;
    if (!attr_done) {
        cudaFuncSetAttribute(gemm_tf32_db<false, false, false>,
                             cudaFuncAttributeMaxDynamicSharedMemorySize, (int)GEMM_SMEM);
        cudaFuncSetAttribute(gemm_tf32_db<true, true, true>,
                             cudaFuncAttributeMaxDynamicSharedMemorySize, (int)GEMM_SMEM);
        cudaFuncSetAttribute(gemm_tf32_db<true, false, false>,
                             cudaFuncAttributeMaxDynamicSharedMemorySize, (int)GEMM_SMEM);
        attr_done = true;
    }

    // K-1: tf32-round the weights
    prep_kernel<<<(DBODY + 256) * HID / 256, 256>>>(W1, W2, Wr);

    // K0: segment lists
    seg_kernel<<<1, 32>>>(eto);

    // K1: pack inputs + segment max (tf32-rounded outputs)
    pack_kernel<<<NNODE * NBATCH, 128>>>(obs, ef, iso, isof);

    // K2: C_body = body @ W1r[:64,:]   (M=8192, K=64, N=256)
    gemm_tf32_db<false, false, false><<<dim3(2, NBATCH / 128), 256, GEMM_SMEM>>>(
        obs, OBS_LD, (const float*)pW1r, HID, (float*)pCbody, HID, DBODY,
        nullptr, nullptr, 0);

    // K3: H = tf32(relu(Xnf @ W1r[64:,:] + C_body[b] + b1))   (M=98304, K=256)
    gemm_tf32_db<true, true, true><<<dim3(2, NNODE * NBATCH / 128), 256, GEMM_SMEM>>>(
        (const float*)pXnf, 256, (const float*)pW1r + (size_t)DBODY * HID, HID,
        (float*)pH, HID, 256, b1, (const float*)pCbody, NBATCH - 1);

    // K4a: P = relu(H @ W2r + b2)   (M=98304, K=256)
    gemm_tf32_db<true, false, false><<<dim3(2, NNODE * NBATCH / 128), 256, GEMM_SMEM>>>(
        (const float*)pH, HID, (const float*)pW2r, PHI_OUT, (float*)pP, PHI_OUT, HID,
        b2, nullptr, 0);

    // K4b: pooled = tf32(sum_n P_n)
    pool_kernel<<<(NBATCH * PHI_OUT) / 256, 256>>>();

    // K5a: R = relu(pooled @ Wrr + b1_rho)   (M=8192, K=256)
    gemm_tf32_db<true, false, false><<<dim3(2, NBATCH / 128), 256, GEMM_SMEM>>>(
        (const float*)pPooled, PHI_OUT, (const float*)pWrr, HID, (float*)pR, HID, PHI_OUT,
        br, nullptr, 0);

    // K5b: heads
    heads_kernel<<<NBATCH / 32, 256>>>(Wm, bm, Ws, bs, out);
}